// round 15
// baseline (speedup 1.0000x reference)
#include <cuda_runtime.h>
#include <math.h>
#include <stddef.h>
#include <stdint.h>

#define D_MODEL 1024
#define NHEAD   16
#define HDIM    64
#define BATCH   4
#define SEQ     2048
#define MTOT    (BATCH * SEQ)   /* 8192 */
#define BH      (BATCH * NHEAD) /* 64   */
// score scale folded with log2(e) so softmax uses ex2
#define QSCALE  (0.125f * 1.4426950408889634f)

// ---------------- scratch (device globals: allocation-free) ----------------
// g_q: [bh][s][dh]. g_k/g_v: FRAGMENT-PACKED per (bh, ktile32).
// g_xt/g_ctx: packed A-fragment. g_w*t: packed B-fragment.
__device__ __align__(16) float g_q[BH * SEQ * HDIM];
__device__ __align__(16) float g_k[BH * SEQ * HDIM];
__device__ __align__(16) float g_v[BH * SEQ * HDIM];
__device__ __align__(16) float g_ctx[MTOT * D_MODEL];
__device__ __align__(16) float g_xt[MTOT * D_MODEL];
__device__ __align__(16) float g_wqt[D_MODEL * D_MODEL];
__device__ __align__(16) float g_wkt[D_MODEL * D_MODEL];
__device__ __align__(16) float g_wvt[D_MODEL * D_MODEL];
__device__ __align__(16) float g_wot[D_MODEL * D_MODEL];

// ---------------- helpers ----------------
__device__ __forceinline__ unsigned f2tf(float f) {
    unsigned u;
    asm("cvt.rna.tf32.f32 %0, %1;" : "=r"(u) : "f"(f));
    return u;
}
__device__ __forceinline__ float ex2(float x) {
    float y;
    asm("ex2.approx.f32 %0, %1;" : "=f"(y) : "f"(x));
    return y;
}
__device__ __forceinline__ void mma_tf32(float d[4], const unsigned a[4], const unsigned b[2]) {
    asm volatile("mma.sync.aligned.m16n8k8.row.col.f32.tf32.tf32.f32 "
        "{%0,%1,%2,%3}, {%4,%5,%6,%7}, {%8,%9}, {%0,%1,%2,%3};\n"
        : "+f"(d[0]), "+f"(d[1]), "+f"(d[2]), "+f"(d[3])
        : "r"(a[0]), "r"(a[1]), "r"(a[2]), "r"(a[3]), "r"(b[0]), "r"(b[1]));
}
__device__ __forceinline__ void cpa16(uint32_t smem, const void* g) {
    asm volatile("cp.async.cg.shared.global [%0], [%1], 16;" :: "r"(smem), "l"(g));
}
#define CP_COMMIT() asm volatile("cp.async.commit_group;")
#define CP_WAIT0()  asm volatile("cp.async.wait_group 0;")
#define CP_WAIT1()  asm volatile("cp.async.wait_group 1;")

// packed K address (32-bit word index): tile = 32 keys x 64 dh = 2048 words
// [dh>>3](x256) [key>>3 &3](x64) [slot=(dh&3)*8+(key&7)](x2) [comp=(dh>>2)&1]
__device__ __forceinline__ int kaddr(int m, int c) {
    int b = m >> 11, s = m & 2047, h = c >> 6, dh = c & 63;
    return ((b * NHEAD + h) << 17) + ((s >> 5) << 11) + ((dh >> 3) << 8)
         + (((s >> 3) & 3) << 6) + (((dh & 3) * 8 + (s & 7)) << 1) + ((dh >> 2) & 1);
}
// packed V uint2 index: [key>>3&3](x256) [dh>>3](x32) [slot=(key&3)*8+(dh&7)]
__device__ __forceinline__ int vaddr2(int m, int c) {
    int b = m >> 11, s = m & 2047, h = c >> 6, dh = c & 63;
    return ((b * NHEAD + h) << 16) + ((s >> 5) << 10) + (((s >> 3) & 3) << 8)
         + ((dh >> 3) << 5) + ((s & 3) * 8 + (dh & 7));
}

// ---------------------------------------------------------------------------
// Fused tf32 pre-pack of x (A-fragments) and weights (B-fragments).
// ---------------------------------------------------------------------------
#define NX4 (MTOT * D_MODEL / 4)
#define NB2 (D_MODEL * D_MODEL / 2)
__global__ void pack_all_kernel(
    const float* __restrict__ x,  const float* __restrict__ wq,
    const float* __restrict__ wk, const float* __restrict__ wv,
    const float* __restrict__ wo)
{
    int i = blockIdx.x * blockDim.x + threadIdx.x;
    if (i < NX4) {
        int lane = i & 31;
        int st   = (i >> 5) & 7;
        int ks   = (i >> 8) & 1;
        int chunk = (i >> 9) & 63;
        int mblk  = i >> 15;
        int r = st * 16 + (lane >> 2);
        int c = chunk * 16 + ks * 8 + (lane & 3);
        const float* base = x + (size_t)(mblk * 128) * 1024;
        uint4 o;
        o.x = f2tf(base[(size_t)r * 1024 + c]);
        o.y = f2tf(base[(size_t)(r + 8) * 1024 + c]);
        o.z = f2tf(base[(size_t)r * 1024 + c + 4]);
        o.w = f2tf(base[(size_t)(r + 8) * 1024 + c + 4]);
        ((uint4*)g_xt)[i] = o;
    } else {
        int j = i - NX4;
        int w = j >> 19;
        int idx = j & (NB2 - 1);
        const float* s = (w == 0) ? wq : (w == 1) ? wk : (w == 2) ? wv : wo;
        float* d = (w == 0) ? g_wqt : (w == 1) ? g_wkt : (w == 2) ? g_wvt : g_wot;
        int lane = idx & 31;
        int nt   = (idx >> 5) & 15;
        int ks   = (idx >> 9) & 1;
        int chunk = (idx >> 10) & 63;
        int nblk  = idx >> 16;
        int n = nblk * 128 + nt * 8 + (lane >> 2);
        int k = chunk * 16 + ks * 8 + (lane & 3);
        uint2 o;
        o.x = f2tf(s[(size_t)n * 1024 + k]);
        o.y = f2tf(s[(size_t)n * 1024 + k + 4]);
        ((uint2*)d)[idx] = o;
    }
}

// ---------------------------------------------------------------------------
// 128x128x1024 GEMM core on packed operands (unchanged from R14).
// ---------------------------------------------------------------------------
#define BUFW 2048
#define NCHK 64
__device__ __forceinline__ void gemm_core(
    const float* __restrict__ A, const float* __restrict__ W,
    int mblk, int nblk, unsigned* As, unsigned* Ws,
    float acc[4][8][4], int t)
{
    const int lane = t & 31;
    const int warp = t >> 5;
    const float* aC = A + (size_t)mblk * (NCHK * BUFW);
    const float* wC = W + (size_t)nblk * (NCHK * BUFW);
    const uint32_t sA = (uint32_t)__cvta_generic_to_shared(As);
    const uint32_t sW = (uint32_t)__cvta_generic_to_shared(Ws);
    const int BUFB = BUFW * 4;

#pragma unroll
    for (int st = 0; st < 2; st++) {
#pragma unroll
        for (int it = 0; it < 4; it++) {
            int g = t + 128 * it;
            cpa16(sA + st * BUFB + g * 16, aC + st * BUFW + g * 4);
            cpa16(sW + st * BUFB + g * 16, wC + st * BUFW + g * 4);
        }
        CP_COMMIT();
    }

    const unsigned* aF = As + ((warp >> 1) << 9) + lane * 4;
    const unsigned* bF = Ws + ((warp & 1) << 9) + lane * 2;

    int bufc = 0, bufn = 2;
#pragma unroll 1
    for (int c = 0; c < NCHK; c++) {
        CP_WAIT1();
        __syncthreads();
        int cn = c + 2;
        if (cn < NCHK) {
#pragma unroll
            for (int it = 0; it < 4; it++) {
                int g = t + 128 * it;
                cpa16(sA + bufn * BUFB + g * 16, aC + (size_t)cn * BUFW + g * 4);
                cpa16(sW + bufn * BUFB + g * 16, wC + (size_t)cn * BUFW + g * 4);
            }
        }
        CP_COMMIT();
        const unsigned* ap = aF + bufc * BUFW;
        const unsigned* bp = bF + bufc * BUFW;
#pragma unroll
        for (int ks = 0; ks < 2; ks++) {
            uint4 av[4];
            uint2 bv[8];
#pragma unroll
            for (int mt = 0; mt < 4; mt++)
                av[mt] = *(const uint4*)(ap + ks * 1024 + mt * 128);
#pragma unroll
            for (int nt = 0; nt < 8; nt++)
                bv[nt] = *(const uint2*)(bp + ks * 1024 + nt * 64);
#pragma unroll
            for (int mt = 0; mt < 4; mt++)
#pragma unroll
                for (int nt = 0; nt < 8; nt++)
                    mma_tf32(acc[mt][nt], (const unsigned*)&av[mt], (const unsigned*)&bv[nt]);
        }
        bufc = (bufc == 2) ? 0 : bufc + 1;
        bufn = (bufn == 2) ? 0 : bufn + 1;
    }
}

// ---------------------------------------------------------------------------
// Kernel 1: fused QKV projection. Q -> natural layout (scaled);
// K, V -> attention fragment-packed layouts.
// ---------------------------------------------------------------------------
__global__ __launch_bounds__(128, 2) void qkv_kernel(
    const float* __restrict__ bq, const float* __restrict__ bk,
    const float* __restrict__ bv)
{
    __shared__ unsigned As[3 * BUFW];
    __shared__ unsigned Ws[3 * BUFW];
    const int t = threadIdx.x;
    const int which = blockIdx.x >> 3;
    const int nblk = blockIdx.x & 7;
    const int mblk = blockIdx.y;

    const float* W    = (which == 0) ? g_wqt : (which == 1) ? g_wkt : g_wvt;
    const float* bias = (which == 0) ? bq : (which == 1) ? bk : bv;

    float acc[4][8][4];
#pragma unroll
    for (int i = 0; i < 4; i++)
#pragma unroll
        for (int j = 0; j < 8; j++)
#pragma unroll
            for (int k = 0; k < 4; k++) acc[i][j][k] = 0.f;

    gemm_core(g_xt, W, mblk, nblk, As, Ws, acc, t);

    const int lane = t & 31, warp = t >> 5;
    const int lq = lane >> 2, lv = lane & 3;
    const int wm = (warp >> 1) * 64, wn = (warp & 1) * 64;
    const int mBase = mblk * 128, nBase = nblk * 128;

    if (which == 0) {
        // Q: natural [bh][s][dh], pre-scaled
#pragma unroll
        for (int mt = 0; mt < 4; mt++) {
            int m0 = mBase + wm + mt * 16 + lq;
            int b0i = m0 >> 11, s0 = m0 & 2047;
            int m1 = m0 + 8;
            int b1i = m1 >> 11, s1 = m1 & 2047;
#pragma unroll
            for (int nt = 0; nt < 8; nt++) {
                int col = nBase + wn + nt * 8 + 2 * lv;
                float2 bv2 = *(const float2*)(bias + col);
                int h = col >> 6, dh = col & 63;
                float2 r0, r1;
                r0.x = __uint_as_float(f2tf((acc[mt][nt][0] + bv2.x) * QSCALE));
                r0.y = __uint_as_float(f2tf((acc[mt][nt][1] + bv2.y) * QSCALE));
                *(float2*)(g_q + ((size_t)(b0i * NHEAD + h) * SEQ + s0) * 64 + dh) = r0;
                r1.x = __uint_as_float(f2tf((acc[mt][nt][2] + bv2.x) * QSCALE));
                r1.y = __uint_as_float(f2tf((acc[mt][nt][3] + bv2.y) * QSCALE));
                *(float2*)(g_q + ((size_t)(b1i * NHEAD + h) * SEQ + s1) * 64 + dh) = r1;
            }
        }
    } else if (which == 1) {
        // K: fragment-packed, 4x STG.32 per (mt, nt)
        unsigned* kw = (unsigned*)g_k;
#pragma unroll
        for (int mt = 0; mt < 4; mt++) {
            int m0 = mBase + wm + mt * 16 + lq;
            int m1 = m0 + 8;
#pragma unroll
            for (int nt = 0; nt < 8; nt++) {
                int col = nBase + wn + nt * 8 + 2 * lv;
                float2 bv2 = *(const float2*)(bias + col);
                kw[kaddr(m0, col)]     = f2tf(acc[mt][nt][0] + bv2.x);
                kw[kaddr(m0, col + 1)] = f2tf(acc[mt][nt][1] + bv2.y);
                kw[kaddr(m1, col)]     = f2tf(acc[mt][nt][2] + bv2.x);
                kw[kaddr(m1, col + 1)] = f2tf(acc[mt][nt][3] + bv2.y);
            }
        }
    } else {
        // V: fragment-packed; {key, key+4} pair spans lanes (lq, lq^4) -> shfl
        float* vw = (float*)g_v;
#pragma unroll
        for (int mt = 0; mt < 4; mt++) {
            int m0 = mBase + wm + mt * 16 + lq;
            int m1 = m0 + 8;
#pragma unroll
            for (int nt = 0; nt < 8; nt++) {
                int col = nBase + wn + nt * 8 + 2 * lv;
                float2 bv2 = *(const float2*)(bias + col);
                float w0 = __uint_as_float(f2tf(acc[mt][nt][0] + bv2.x));
                float w1 = __uint_as_float(f2tf(acc[mt][nt][1] + bv2.y));
                float w2 = __uint_as_float(f2tf(acc[mt][nt][2] + bv2.x));
                float w3 = __uint_as_float(f2tf(acc[mt][nt][3] + bv2.y));
                float o0 = __shfl_xor_sync(0xffffffffu, w0, 16);
                float o1 = __shfl_xor_sync(0xffffffffu, w1, 16);
                float o2 = __shfl_xor_sync(0xffffffffu, w2, 16);
                float o3 = __shfl_xor_sync(0xffffffffu, w3, 16);
                if (lq < 4) {
                    *(float2*)(vw + (size_t)vaddr2(m0, col) * 2) = make_float2(w0, o0);
                    *(float2*)(vw + (size_t)vaddr2(m1, col) * 2) = make_float2(w2, o2);
                } else {
                    *(float2*)(vw + (size_t)vaddr2(m0 - 4, col + 1) * 2) = make_float2(o1, w1);
                    *(float2*)(vw + (size_t)vaddr2(m1 - 4, col + 1) * 2) = make_float2(o3, w3);
                }
            }
        }
    }
}

// ---------------------------------------------------------------------------
// Kernel 2: flash attention, no-max softmax, all operands fragment-packed.
// grid (16, 64), 128 threads (4 warps x 32 q-rows).
// Smem: Ks 2x8KB + Vs 2x8KB + Ps 16KB = 48KB.
// ---------------------------------------------------------------------------
__global__ __launch_bounds__(128, 2) void attn_kernel()
{
    __shared__ unsigned Ks[2][2048];
    __shared__ unsigned Vs[2][2048];
    __shared__ unsigned Ps[4096];   // 4 warps x 1024 words

    const int t = threadIdx.x;
    const int lane = t & 31, warp = t >> 5;
    const int lq = lane >> 2, lv = lane & 3;
    const int qBase = blockIdx.x * 128;
    const int bh    = blockIdx.y;
    const float* kpk = g_k + (size_t)bh * (SEQ * HDIM);
    const float* vpk = g_v + (size_t)bh * (SEQ * HDIM);
    const unsigned* qb = (const unsigned*)g_q + (size_t)bh * (SEQ * HDIM);

    const uint32_t sK = (uint32_t)__cvta_generic_to_shared(&Ks[0][0]);
    const uint32_t sV = (uint32_t)__cvta_generic_to_shared(&Vs[0][0]);

    // prologue copy: tile 0 (pure linear)
#pragma unroll
    for (int i = 0; i < 4; i++) {
        int g = t + 128 * i;
        cpa16(sK + g * 16, kpk + g * 4);
        cpa16(sV + g * 16, vpk + g * 4);
    }
    CP_COMMIT();

    // fragment slot offset (words) shared by K and V loads
    const int wS = ((lane & 3) * 8 + (lane >> 2)) * 2;
    // P load base (group permutation g' = g ^ ((g>>3)&3))
    const unsigned* pPl = Ps + warp * 1024 + (lane ^ ((lane >> 3) & 3)) * 4;
    // P store bases
    unsigned* pS1;
    unsigned* pS2;
    {
        int g1 = lq * 4 + ((2 * lv) & 3);
        int g2 = lq * 4 + ((2 * lv + 1) & 3);
        int xq = (lq >> 1) & 3;
        int sl = (lv >> 1) * 2;
        pS1 = Ps + warp * 1024 + (g1 ^ xq) * 4 + sl;
        pS2 = Ps + warp * 1024 + (g2 ^ xq) * 4 + sl;
    }

    // Q fragments (pre-scaled, pre-rounded)
    unsigned qf[2][8][4];
#pragma unroll
    for (int mt = 0; mt < 2; mt++) {
        int r = qBase + warp * 32 + mt * 16 + lq;
#pragma unroll
        for (int ks = 0; ks < 8; ks++) {
            qf[mt][ks][0] = qb[(size_t)r * 64 + ks * 8 + lv];
            qf[mt][ks][1] = qb[(size_t)(r + 8) * 64 + ks * 8 + lv];
            qf[mt][ks][2] = qb[(size_t)r * 64 + ks * 8 + lv + 4];
            qf[mt][ks][3] = qb[(size_t)(r + 8) * 64 + ks * 8 + lv + 4];
        }
    }

    float O[2][8][4];
#pragma unroll
    for (int mt = 0; mt < 2; mt++)
#pragma unroll
        for (int nt = 0; nt < 8; nt++)
#pragma unroll
            for (int k = 0; k < 4; k++) O[mt][nt][k] = 0.f;
    float l_part[4] = {0.f, 0.f, 0.f, 0.f};

#pragma unroll 1
    for (int kt = 0; kt < SEQ / 32; kt++) {
        CP_WAIT0();
        __syncthreads();
        if (kt + 1 < SEQ / 32) {
            int bo = ((kt + 1) & 1) * 8192;
            size_t gb = (size_t)(kt + 1) * 2048;
#pragma unroll
            for (int i = 0; i < 4; i++) {
                int g = t + 128 * i;
                cpa16(sK + bo + g * 16, kpk + gb + g * 4);
                cpa16(sV + bo + g * 16, vpk + gb + g * 4);
            }
            CP_COMMIT();
        }
        const unsigned* pKb = Ks[kt & 1] + wS;
        const unsigned* pVb = Vs[kt & 1] + wS;

        // S = Q K^T (packed K: uint2 per (ks, nt))
        float s[2][4][4];
#pragma unroll
        for (int mt = 0; mt < 2; mt++)
#pragma unroll
            for (int nt = 0; nt < 4; nt++)
#pragma unroll
                for (int k = 0; k < 4; k++) s[mt][nt][k] = 0.f;
#pragma unroll
        for (int ks = 0; ks < 8; ks++) {
            uint2 bf[4];
#pragma unroll
            for (int nt = 0; nt < 4; nt++)
                bf[nt] = *(const uint2*)(pKb + ks * 256 + nt * 64);
#pragma unroll
            for (int mt = 0; mt < 2; mt++)
#pragma unroll
                for (int nt = 0; nt < 4; nt++)
                    mma_tf32(s[mt][nt], qf[mt][ks], (const unsigned*)&bf[nt]);
        }

        // P = 2^s, accumulate l, store P packed (A-fragment order)
#pragma unroll
        for (int mt = 0; mt < 2; mt++) {
#pragma unroll
            for (int nt = 0; nt < 4; nt++) {
                float e0 = ex2(s[mt][nt][0]);
                float e1 = ex2(s[mt][nt][1]);
                float e2 = ex2(s[mt][nt][2]);
                float e3 = ex2(s[mt][nt][3]);
                l_part[mt * 2]     += e0 + e1;
                l_part[mt * 2 + 1] += e2 + e3;
                *(uint2*)(pS1 + mt * 512 + nt * 128) = make_uint2(f2tf(e0), f2tf(e2));
                *(uint2*)(pS2 + mt * 512 + nt * 128) = make_uint2(f2tf(e1), f2tf(e3));
            }
        }
        __syncwarp();

        // O += P V  (packed P: uint4; packed V: uint2)
#pragma unroll
        for (int kc = 0; kc < 4; kc++) {
            uint4 pa[2];
            pa[0] = *(const uint4*)(pPl + kc * 128);
            pa[1] = *(const uint4*)(pPl + 512 + kc * 128);
#pragma unroll
            for (int nt = 0; nt < 8; nt++) {
                uint2 vb = *(const uint2*)(pVb + kc * 512 + nt * 64);
                mma_tf32(O[0][nt], (const unsigned*)&pa[0], (const unsigned*)&vb);
                mma_tf32(O[1][nt], (const unsigned*)&pa[1], (const unsigned*)&vb);
            }
        }
    }

    // final l reduction (quad)
#pragma unroll
    for (int ri = 0; ri < 4; ri++) {
        l_part[ri] += __shfl_xor_sync(0xffffffffu, l_part[ri], 1);
        l_part[ri] += __shfl_xor_sync(0xffffffffu, l_part[ri], 2);
    }

    // epilogue: ctx in packed-A layout (unchanged from R14)
    const int bIdx = bh >> 4, h = bh & 15;
    const int mblk = bIdx * 16 + blockIdx.x;
    const int rloc = warp * 32 + lq;
    (void)rloc;
#pragma unroll
    for (int mt = 0; mt < 2; mt++) {
        const int st = warp * 2 + mt;
        float invA = 1.f / l_part[mt * 2];
        float invB = 1.f / l_part[mt * 2 + 1];
#pragma unroll
        for (int nt = 0; nt < 8; nt++) {
            int chunkv = h * 4 + (nt >> 1);
            int ksv = nt & 1;
            int lane0 = lq * 4 + ((2 * lv) & 3);
            int s0 = 2 * (lv >> 1);
            float* base = g_ctx + ((size_t)mblk * 64 + chunkv) * 2048 + ksv * 1024 + st * 128;
            float2 p0, p1;
            p0.x = __uint_as_float(f2tf(O[mt][nt][0] * invA));
            p0.y = __uint_as_float(f2tf(O[mt][nt][2] * invB));
            *(float2*)(base + lane0 * 4 + s0) = p0;
            p1.x = __uint_as_float(f2tf(O[mt][nt][1] * invA));
            p1.y = __uint_as_float(f2tf(O[mt][nt][3] * invB));
            *(float2*)(base + (lane0 + 1) * 4 + s0) = p1;
        }
    }
}

// ---------------------------------------------------------------------------
// Kernel 3: output projection. grid (8, 64), 128 threads. (unchanged)
// ---------------------------------------------------------------------------
__global__ __launch_bounds__(128, 2) void oproj_kernel(
    const float* __restrict__ bo, float* __restrict__ out)
{
    __shared__ unsigned As[3 * BUFW];
    __shared__ unsigned Ws[3 * BUFW];
    const int t = threadIdx.x;
    const int nblk = blockIdx.x;
    const int mblk = blockIdx.y;

    float acc[4][8][4];
#pragma unroll
    for (int i = 0; i < 4; i++)
#pragma unroll
        for (int j = 0; j < 8; j++)
#pragma unroll
            for (int k = 0; k < 4; k++) acc[i][j][k] = 0.f;

    gemm_core(g_ctx, g_wot, mblk, nblk, As, Ws, acc, t);

    const int lane = t & 31, warp = t >> 5;
    const int lq = lane >> 2, lv = lane & 3;
    const int wm = (warp >> 1) * 64, wn = (warp & 1) * 64;
    const int mBase = mblk * 128, nBase = nblk * 128;

#pragma unroll
    for (int mt = 0; mt < 4; mt++) {
        int m0 = mBase + wm + mt * 16 + lq;
        int m1 = m0 + 8;
#pragma unroll
        for (int nt = 0; nt < 8; nt++) {
            int col = nBase + wn + nt * 8 + 2 * lv;
            float2 bv2 = *(const float2*)(bo + col);
            float2 r0 = make_float2(acc[mt][nt][0] + bv2.x, acc[mt][nt][1] + bv2.y);
            *(float2*)(out + (size_t)m0 * D_MODEL + col) = r0;
            float2 r1 = make_float2(acc[mt][nt][2] + bv2.x, acc[mt][nt][3] + bv2.y);
            *(float2*)(out + (size_t)m1 * D_MODEL + col) = r1;
        }
    }
}

// ---------------------------------------------------------------------------
extern "C" void kernel_launch(void* const* d_in, const int* in_sizes, int n_in,
                              void* d_out, int out_size)
{
    (void)in_sizes; (void)n_in; (void)out_size;
    const float* x  = (const float*)d_in[0];
    const float* wq = (const float*)d_in[1];
    const float* bq = (const float*)d_in[2];
    const float* wk = (const float*)d_in[3];
    const float* bk = (const float*)d_in[4];
    const float* wv = (const float*)d_in[5];
    const float* bv = (const float*)d_in[6];
    const float* wo = (const float*)d_in[7];
    const float* bo = (const float*)d_in[8];
    float* out = (float*)d_out;

    const int ntot = NX4 + 4 * NB2;    // 4194304
    pack_all_kernel<<<ntot / 256, 256>>>(x, wq, wk, wv, wo);

    qkv_kernel<<<dim3(24, 64), 128>>>(bq, bk, bv);
    attn_kernel<<<dim3(SEQ / 128, BH), 128>>>();
    oproj_kernel<<<dim3(8, 64), 128>>>(bo, out);
}

// round 16
// speedup vs baseline: 1.0590x; 1.0590x over previous
#include <cuda_runtime.h>
#include <math.h>
#include <stddef.h>
#include <stdint.h>

#define D_MODEL 1024
#define NHEAD   16
#define HDIM    64
#define BATCH   4
#define SEQ     2048
#define MTOT    (BATCH * SEQ)   /* 8192 */
#define BH      (BATCH * NHEAD) /* 64   */
// score scale folded with log2(e) so softmax uses ex2
#define QSCALE  (0.125f * 1.4426950408889634f)

// ---------------- scratch (device globals: allocation-free) ----------------
// g_q/g_k/g_v: attention layout [bh][s][dh].
// g_xt/g_ctx: packed A-fragment. g_w*t: packed B-fragment.
__device__ __align__(16) float g_q[BH * SEQ * HDIM];
__device__ __align__(16) float g_k[BH * SEQ * HDIM];
__device__ __align__(16) float g_v[BH * SEQ * HDIM];
__device__ __align__(16) float g_ctx[MTOT * D_MODEL];
__device__ __align__(16) float g_xt[MTOT * D_MODEL];
__device__ __align__(16) float g_wqt[D_MODEL * D_MODEL];
__device__ __align__(16) float g_wkt[D_MODEL * D_MODEL];
__device__ __align__(16) float g_wvt[D_MODEL * D_MODEL];
__device__ __align__(16) float g_wot[D_MODEL * D_MODEL];

// ---------------- helpers ----------------
__device__ __forceinline__ unsigned f2tf(float f) {
    unsigned u;
    asm("cvt.rna.tf32.f32 %0, %1;" : "=r"(u) : "f"(f));
    return u;
}
__device__ __forceinline__ float ex2(float x) {
    float y;
    asm("ex2.approx.f32 %0, %1;" : "=f"(y) : "f"(x));
    return y;
}
__device__ __forceinline__ void mma_tf32(float d[4], const unsigned a[4], const unsigned b[2]) {
    asm volatile("mma.sync.aligned.m16n8k8.row.col.f32.tf32.tf32.f32 "
        "{%0,%1,%2,%3}, {%4,%5,%6,%7}, {%8,%9}, {%0,%1,%2,%3};\n"
        : "+f"(d[0]), "+f"(d[1]), "+f"(d[2]), "+f"(d[3])
        : "r"(a[0]), "r"(a[1]), "r"(a[2]), "r"(a[3]), "r"(b[0]), "r"(b[1]));
}
__device__ __forceinline__ void cpa16(uint32_t smem, const void* g) {
    asm volatile("cp.async.cg.shared.global [%0], [%1], 16;" :: "r"(smem), "l"(g));
}
#define CP_COMMIT() asm volatile("cp.async.commit_group;")
#define CP_WAIT0()  asm volatile("cp.async.wait_group 0;")
#define CP_WAIT1()  asm volatile("cp.async.wait_group 1;")

// ---------------------------------------------------------------------------
// Fused tf32 pre-pack of x (A-fragments) and weights (B-fragments).
// ---------------------------------------------------------------------------
#define NX4 (MTOT * D_MODEL / 4)
#define NB2 (D_MODEL * D_MODEL / 2)
__global__ void pack_all_kernel(
    const float* __restrict__ x,  const float* __restrict__ wq,
    const float* __restrict__ wk, const float* __restrict__ wv,
    const float* __restrict__ wo)
{
    int i = blockIdx.x * blockDim.x + threadIdx.x;
    if (i < NX4) {
        int lane = i & 31;
        int st   = (i >> 5) & 7;
        int ks   = (i >> 8) & 1;
        int chunk = (i >> 9) & 63;
        int mblk  = i >> 15;
        int r = st * 16 + (lane >> 2);
        int c = chunk * 16 + ks * 8 + (lane & 3);
        const float* base = x + (size_t)(mblk * 128) * 1024;
        uint4 o;
        o.x = f2tf(base[(size_t)r * 1024 + c]);
        o.y = f2tf(base[(size_t)(r + 8) * 1024 + c]);
        o.z = f2tf(base[(size_t)r * 1024 + c + 4]);
        o.w = f2tf(base[(size_t)(r + 8) * 1024 + c + 4]);
        ((uint4*)g_xt)[i] = o;
    } else {
        int j = i - NX4;
        int w = j >> 19;
        int idx = j & (NB2 - 1);
        const float* s = (w == 0) ? wq : (w == 1) ? wk : (w == 2) ? wv : wo;
        float* d = (w == 0) ? g_wqt : (w == 1) ? g_wkt : (w == 2) ? g_wvt : g_wot;
        int lane = idx & 31;
        int nt   = (idx >> 5) & 15;
        int ks   = (idx >> 9) & 1;
        int chunk = (idx >> 10) & 63;
        int nblk  = idx >> 16;
        int n = nblk * 128 + nt * 8 + (lane >> 2);
        int k = chunk * 16 + ks * 8 + (lane & 3);
        uint2 o;
        o.x = f2tf(s[(size_t)n * 1024 + k]);
        o.y = f2tf(s[(size_t)n * 1024 + k + 4]);
        ((uint2*)d)[idx] = o;
    }
}

// ---------------------------------------------------------------------------
// 128x128x1024 GEMM core on packed operands. GKC=32: each pipeline stage
// holds TWO 16-wide chunks (16KB per array), 3 stages = 96KB dynamic smem.
// Halves barrier count (32 iters) and doubles mma burst (128/warp/iter).
// ---------------------------------------------------------------------------
#define BUFW 4096              /* words per stage per array (16KB) */
#define NSTEP 32
__device__ __forceinline__ void gemm_core(
    const float* __restrict__ A, const float* __restrict__ W,
    int mblk, int nblk, unsigned* As, unsigned* Ws,  // each 3*BUFW words
    float acc[4][8][4], int t)
{
    const int lane = t & 31;
    const int warp = t >> 5;
    const float* aC = A + (size_t)mblk * (NSTEP * BUFW);
    const float* wC = W + (size_t)nblk * (NSTEP * BUFW);
    const uint32_t sA = (uint32_t)__cvta_generic_to_shared(As);
    const uint32_t sW = (uint32_t)__cvta_generic_to_shared(Ws);
    const int BUFB = BUFW * 4;

    // prologue: stages 0 and 1
#pragma unroll
    for (int st = 0; st < 2; st++) {
#pragma unroll
        for (int it = 0; it < 8; it++) {
            int g = t + 128 * it;
            cpa16(sA + st * BUFB + g * 16, aC + (size_t)st * BUFW + g * 4);
            cpa16(sW + st * BUFB + g * 16, wC + (size_t)st * BUFW + g * 4);
        }
        CP_COMMIT();
    }

    const unsigned* aF = As + ((warp >> 1) << 9) + lane * 4;
    const unsigned* bF = Ws + ((warp & 1) << 9) + lane * 2;

    int bufc = 0, bufn = 2;
#pragma unroll 1
    for (int c = 0; c < NSTEP; c++) {
        CP_WAIT1();
        __syncthreads();
        int cn = c + 2;
        if (cn < NSTEP) {
#pragma unroll
            for (int it = 0; it < 8; it++) {
                int g = t + 128 * it;
                cpa16(sA + bufn * BUFB + g * 16, aC + (size_t)cn * BUFW + g * 4);
                cpa16(sW + bufn * BUFB + g * 16, wC + (size_t)cn * BUFW + g * 4);
            }
        }
        CP_COMMIT();
#pragma unroll
        for (int sub = 0; sub < 2; sub++) {
            const unsigned* ap = aF + bufc * BUFW + sub * 2048;
            const unsigned* bp = bF + bufc * BUFW + sub * 2048;
#pragma unroll
            for (int ks = 0; ks < 2; ks++) {
                uint4 av[4];
                uint2 bv[8];
#pragma unroll
                for (int mt = 0; mt < 4; mt++)
                    av[mt] = *(const uint4*)(ap + ks * 1024 + mt * 128);
#pragma unroll
                for (int nt = 0; nt < 8; nt++)
                    bv[nt] = *(const uint2*)(bp + ks * 1024 + nt * 64);
#pragma unroll
                for (int mt = 0; mt < 4; mt++)
#pragma unroll
                    for (int nt = 0; nt < 8; nt++)
                        mma_tf32(acc[mt][nt], (const unsigned*)&av[mt], (const unsigned*)&bv[nt]);
            }
        }
        bufc = (bufc == 2) ? 0 : bufc + 1;
        bufn = (bufn == 2) ? 0 : bufn + 1;
    }
}

// ---------------------------------------------------------------------------
// Kernel 1: fused QKV projection. grid (24, 64), 128 threads, 96KB dyn smem.
// K/V written in natural attention layout (R14 form).
// ---------------------------------------------------------------------------
__global__ __launch_bounds__(128, 2) void qkv_kernel(
    const float* __restrict__ bq, const float* __restrict__ bk,
    const float* __restrict__ bv)
{
    extern __shared__ unsigned dynsm[];
    unsigned* As = dynsm;
    unsigned* Ws = dynsm + 3 * BUFW;
    const int t = threadIdx.x;
    const int which = blockIdx.x >> 3;
    const int nblk = blockIdx.x & 7;
    const int mblk = blockIdx.y;

    const float* W    = (which == 0) ? g_wqt : (which == 1) ? g_wkt : g_wvt;
    const float* bias = (which == 0) ? bq : (which == 1) ? bk : bv;
    float* dst        = (which == 0) ? g_q : (which == 1) ? g_k : g_v;
    const float scale = (which == 0) ? QSCALE : 1.0f;

    float acc[4][8][4];
#pragma unroll
    for (int i = 0; i < 4; i++)
#pragma unroll
        for (int j = 0; j < 8; j++)
#pragma unroll
            for (int k = 0; k < 4; k++) acc[i][j][k] = 0.f;

    gemm_core(g_xt, W, mblk, nblk, As, Ws, acc, t);

    const int lane = t & 31, warp = t >> 5;
    const int lq = lane >> 2, lv = lane & 3;
    const int wm = (warp >> 1) * 64, wn = (warp & 1) * 64;
    const int mBase = mblk * 128, nBase = nblk * 128;

#pragma unroll
    for (int mt = 0; mt < 4; mt++) {
        int m0 = mBase + wm + mt * 16 + lq;
        int b0i = m0 >> 11, s0 = m0 & 2047;
        int m1 = m0 + 8;
        int b1i = m1 >> 11, s1 = m1 & 2047;
#pragma unroll
        for (int nt = 0; nt < 8; nt++) {
            int col = nBase + wn + nt * 8 + 2 * lv;
            float2 bv2 = *(const float2*)(bias + col);
            int h = col >> 6, dh = col & 63;
            float2 r0, r1;
            r0.x = __uint_as_float(f2tf((acc[mt][nt][0] + bv2.x) * scale));
            r0.y = __uint_as_float(f2tf((acc[mt][nt][1] + bv2.y) * scale));
            *(float2*)(dst + ((size_t)(b0i * NHEAD + h) * SEQ + s0) * 64 + dh) = r0;
            r1.x = __uint_as_float(f2tf((acc[mt][nt][2] + bv2.x) * scale));
            r1.y = __uint_as_float(f2tf((acc[mt][nt][3] + bv2.y) * scale));
            *(float2*)(dst + ((size_t)(b1i * NHEAD + h) * SEQ + s1) * 64 + dh) = r1;
        }
    }
}

// ---------------------------------------------------------------------------
// Kernel 2: flash attention (R14 form, unchanged). grid (16, 64), 128 thr.
// ---------------------------------------------------------------------------
__global__ __launch_bounds__(128, 2) void attn_kernel()
{
    __shared__ unsigned Ks[2][32 * 64];
    __shared__ unsigned Vs[2][32 * 64];
    __shared__ unsigned Ps[128 * 32];

    const int t = threadIdx.x;
    const int lane = t & 31, warp = t >> 5;
    const int lq = lane >> 2, lv = lane & 3;
    const int qBase = blockIdx.x * 128;
    const int bh    = blockIdx.y;
    const float* kp = g_k + (size_t)bh * (SEQ * HDIM);
    const float* vp = g_v + (size_t)bh * (SEQ * HDIM);
    const unsigned* qb = (const unsigned*)g_q + (size_t)bh * (SEQ * HDIM);

    int offK[4], offV[4], offS[4];
#pragma unroll
    for (int i = 0; i < 4; i++) {
        int fi = t + 128 * i;
        int cr = fi >> 4, cg = fi & 15;
        offK[i] = (cr * 64 + ((cg ^ (cr & 7)) << 2)) * 4;
        offV[i] = (cr * 64 + ((cg ^ ((cr & 3) << 1)) << 2)) * 4;
        offS[i] = cr * 64 + cg * 4;
    }
    const uint32_t sK = (uint32_t)__cvta_generic_to_shared(&Ks[0][0]);
    const uint32_t sV = (uint32_t)__cvta_generic_to_shared(&Vs[0][0]);

#pragma unroll
    for (int i = 0; i < 4; i++) {
        cpa16(sK + offK[i], kp + offS[i]);
        cpa16(sV + offV[i], vp + offS[i]);
    }
    CP_COMMIT();

    const int rloc = warp * 32 + lq;

    int voff[8];
#pragma unroll
    for (int nt = 0; nt < 8; nt++)
        voff[nt] = ((nt ^ lv) << 3) + ((lq >> 2) << 2) + (lq & 3);
    unsigned* pPsn[4];
    {
        int xs = (lq >> 1) & 3, b0s = lq & 1;
#pragma unroll
        for (int nt = 0; nt < 4; nt++) {
            int xorv = ((nt ^ xs) << 1) + ((lv >> 1) ^ b0s);
            pPsn[nt] = Ps + rloc * 32 + (xorv << 2) + ((lv & 1) << 1);
        }
    }
    const unsigned* pP2 = Ps + rloc * 32 + lv;

    unsigned qf[2][8][4];
#pragma unroll
    for (int mt = 0; mt < 2; mt++) {
        int r = qBase + warp * 32 + mt * 16 + lq;
#pragma unroll
        for (int ks = 0; ks < 8; ks++) {
            qf[mt][ks][0] = qb[(size_t)r * 64 + ks * 8 + lv];
            qf[mt][ks][1] = qb[(size_t)(r + 8) * 64 + ks * 8 + lv];
            qf[mt][ks][2] = qb[(size_t)r * 64 + ks * 8 + lv + 4];
            qf[mt][ks][3] = qb[(size_t)(r + 8) * 64 + ks * 8 + lv + 4];
        }
    }

    float O[2][8][4];
#pragma unroll
    for (int mt = 0; mt < 2; mt++)
#pragma unroll
        for (int nt = 0; nt < 8; nt++)
#pragma unroll
            for (int k = 0; k < 4; k++) O[mt][nt][k] = 0.f;
    float l_part[4] = {0.f, 0.f, 0.f, 0.f};

#pragma unroll 1
    for (int kt = 0; kt < SEQ / 32; kt++) {
        CP_WAIT0();
        __syncthreads();
        if (kt + 1 < SEQ / 32) {
            int bo = ((kt + 1) & 1) * (32 * 64 * 4);
            size_t gb = (size_t)(kt + 1) * 32 * 64;
#pragma unroll
            for (int i = 0; i < 4; i++) {
                cpa16(sK + bo + offK[i], kp + gb + offS[i]);
                cpa16(sV + bo + offV[i], vp + gb + offS[i]);
            }
            CP_COMMIT();
        }
        const unsigned* Kb = Ks[kt & 1];
        const unsigned* Vb = Vs[kt & 1];
        const unsigned* pK = Kb + lq * 64 + lv;
        const unsigned* pVn[8];
#pragma unroll
        for (int nt = 0; nt < 8; nt++) pVn[nt] = Vb + lv * 64 + voff[nt];

        float s[2][4][4];
#pragma unroll
        for (int mt = 0; mt < 2; mt++)
#pragma unroll
            for (int nt = 0; nt < 4; nt++)
#pragma unroll
                for (int k = 0; k < 4; k++) s[mt][nt][k] = 0.f;
#pragma unroll
        for (int ks = 0; ks < 8; ks++) {
            const unsigned* k0 = pK + (((2 * ks) ^ lq) << 2);
            const unsigned* k1 = pK + (((2 * ks + 1) ^ lq) << 2);
            unsigned bf[4][2];
#pragma unroll
            for (int nt = 0; nt < 4; nt++) {
                bf[nt][0] = k0[nt * 512];
                bf[nt][1] = k1[nt * 512];
            }
#pragma unroll
            for (int mt = 0; mt < 2; mt++)
#pragma unroll
                for (int nt = 0; nt < 4; nt++)
                    mma_tf32(s[mt][nt], qf[mt][ks], bf[nt]);
        }

#pragma unroll
        for (int mt = 0; mt < 2; mt++) {
#pragma unroll
            for (int nt = 0; nt < 4; nt++) {
                float e0 = ex2(s[mt][nt][0]);
                float e1 = ex2(s[mt][nt][1]);
                float e2 = ex2(s[mt][nt][2]);
                float e3 = ex2(s[mt][nt][3]);
                l_part[mt * 2]     += e0 + e1;
                l_part[mt * 2 + 1] += e2 + e3;
                *(uint2*)&pPsn[nt][mt * 512]       = make_uint2(f2tf(e0), f2tf(e1));
                *(uint2*)&pPsn[nt][mt * 512 + 256] = make_uint2(f2tf(e2), f2tf(e3));
            }
        }
        __syncwarp();

#pragma unroll
        for (int ks = 0; ks < 4; ks++) {
            const unsigned* p0 = pP2 + (((2 * ks) ^ lq) << 2);
            const unsigned* p1 = pP2 + (((2 * ks + 1) ^ lq) << 2);
            unsigned pa[2][4];
#pragma unroll
            for (int mt = 0; mt < 2; mt++) {
                pa[mt][0] = p0[mt * 512];
                pa[mt][1] = p0[mt * 512 + 256];
                pa[mt][2] = p1[mt * 512];
                pa[mt][3] = p1[mt * 512 + 256];
            }
#pragma unroll
            for (int nt = 0; nt < 8; nt++) {
                unsigned vb[2];
                vb[0] = pVn[nt][ks * 512];
                vb[1] = pVn[nt][ks * 512 + 256];
                mma_tf32(O[0][nt], pa[0], vb);
                mma_tf32(O[1][nt], pa[1], vb);
            }
        }
    }

#pragma unroll
    for (int ri = 0; ri < 4; ri++) {
        l_part[ri] += __shfl_xor_sync(0xffffffffu, l_part[ri], 1);
        l_part[ri] += __shfl_xor_sync(0xffffffffu, l_part[ri], 2);
    }

    // epilogue: ctx in packed-A layout (tf32-rounded)
    const int bIdx = bh >> 4, h = bh & 15;
    const int mblk = bIdx * 16 + blockIdx.x;
#pragma unroll
    for (int mt = 0; mt < 2; mt++) {
        const int st = warp * 2 + mt;
        float invA = 1.f / l_part[mt * 2];
        float invB = 1.f / l_part[mt * 2 + 1];
#pragma unroll
        for (int nt = 0; nt < 8; nt++) {
            int chunkv = h * 4 + (nt >> 1);
            int ksv = nt & 1;
            int lane0 = lq * 4 + ((2 * lv) & 3);
            int s0 = 2 * (lv >> 1);
            float* base = g_ctx + ((size_t)mblk * 64 + chunkv) * 2048 + ksv * 1024 + st * 128;
            float2 p0, p1;
            p0.x = __uint_as_float(f2tf(O[mt][nt][0] * invA));
            p0.y = __uint_as_float(f2tf(O[mt][nt][2] * invB));
            *(float2*)(base + lane0 * 4 + s0) = p0;
            p1.x = __uint_as_float(f2tf(O[mt][nt][1] * invA));
            p1.y = __uint_as_float(f2tf(O[mt][nt][3] * invB));
            *(float2*)(base + (lane0 + 1) * 4 + s0) = p1;
        }
    }
}

// ---------------------------------------------------------------------------
// Kernel 3: output projection. grid (8, 64), 128 threads, 96KB dyn smem.
// ---------------------------------------------------------------------------
__global__ __launch_bounds__(128, 2) void oproj_kernel(
    const float* __restrict__ bo, float* __restrict__ out)
{
    extern __shared__ unsigned dynsm[];
    unsigned* As = dynsm;
    unsigned* Ws = dynsm + 3 * BUFW;
    const int t = threadIdx.x;
    const int nblk = blockIdx.x;
    const int mblk = blockIdx.y;

    float acc[4][8][4];
#pragma unroll
    for (int i = 0; i < 4; i++)
#pragma unroll
        for (int j = 0; j < 8; j++)
#pragma unroll
            for (int k = 0; k < 4; k++) acc[i][j][k] = 0.f;

    gemm_core(g_ctx, g_wot, mblk, nblk, As, Ws, acc, t);

    const int lane = t & 31, warp = t >> 5;
    const int lq = lane >> 2, lv = lane & 3;
    const int wm = (warp >> 1) * 64, wn = (warp & 1) * 64;
    const int mBase = mblk * 128, nBase = nblk * 128;

#pragma unroll
    for (int mt = 0; mt < 4; mt++) {
        int m0 = mBase + wm + mt * 16 + lq;
        int m1 = m0 + 8;
#pragma unroll
        for (int nt = 0; nt < 8; nt++) {
            int col = nBase + wn + nt * 8 + 2 * lv;
            float2 bv2 = *(const float2*)(bo + col);
            float2 r0 = make_float2(acc[mt][nt][0] + bv2.x, acc[mt][nt][1] + bv2.y);
            *(float2*)(out + (size_t)m0 * D_MODEL + col) = r0;
            float2 r1 = make_float2(acc[mt][nt][2] + bv2.x, acc[mt][nt][3] + bv2.y);
            *(float2*)(out + (size_t)m1 * D_MODEL + col) = r1;
        }
    }
}

// ---------------------------------------------------------------------------
extern "C" void kernel_launch(void* const* d_in, const int* in_sizes, int n_in,
                              void* d_out, int out_size)
{
    (void)in_sizes; (void)n_in; (void)out_size;
    const float* x  = (const float*)d_in[0];
    const float* wq = (const float*)d_in[1];
    const float* bq = (const float*)d_in[2];
    const float* wk = (const float*)d_in[3];
    const float* bk = (const float*)d_in[4];
    const float* wv = (const float*)d_in[5];
    const float* bv = (const float*)d_in[6];
    const float* wo = (const float*)d_in[7];
    const float* bo = (const float*)d_in[8];
    float* out = (float*)d_out;

    const int DYNSMEM = 3 * BUFW * 2 * 4;   // 98304 bytes
    cudaFuncSetAttribute(qkv_kernel,  cudaFuncAttributeMaxDynamicSharedMemorySize, DYNSMEM);
    cudaFuncSetAttribute(oproj_kernel, cudaFuncAttributeMaxDynamicSharedMemorySize, DYNSMEM);

    const int ntot = NX4 + 4 * NB2;    // 4194304
    pack_all_kernel<<<ntot / 256, 256>>>(x, wq, wk, wv, wo);

    qkv_kernel<<<dim3(24, 64), 128, DYNSMEM>>>(bq, bk, bv);
    attn_kernel<<<dim3(SEQ / 128, BH), 128>>>();
    oproj_kernel<<<dim3(8, 64), 128, DYNSMEM>>>(bo, out);
}